// round 2
// baseline (speedup 1.0000x reference)
#include <cuda_runtime.h>
#include <cstdint>

// ============================================================
// W8A8 linear: out[M,N] = xs * (Xq[M,K] @ Wq[N,K]^T) * wsc[n] + bias[n]
//   M = 8192, N = 4096, K = 4096
// Base-sm_103 path (no tcgen05 — harness compiles via compute_103):
//   int8 mma.sync.m16n8k32 + cp.async multistage pipeline + ldmatrix.
// Integer dot products are exact in s32 (<= 4096*127^2 ~ 6.6e7).
// ============================================================

#define MM 8192
#define NN 4096
#define KK 4096

#define BM 128
#define BN 256
#define BK 128
#define STAGES 3
#define KITERS (KK / BK)      // 32
#define NTHREADS 512

// ---- device scratch: quantized int8 operands ----
__device__ __align__(128) int8_t g_xq[(size_t)MM * KK];
__device__ __align__(128) int8_t g_wq[(size_t)NN * KK];

// ============================================================
// PTX helpers (base-arch only)
// ============================================================
__device__ __forceinline__ uint32_t smem_to_u32(const void* p) {
    uint32_t a;
    asm("{ .reg .u64 t; cvta.to.shared.u64 t, %1; cvt.u32.u64 %0, t; }"
        : "=r"(a) : "l"(p));
    return a;
}

__device__ __forceinline__ void cp_async16(uint32_t dst, const void* src) {
    asm volatile("cp.async.cg.shared.global [%0], [%1], 16;"
                 :: "r"(dst), "l"(src) : "memory");
}
#define CP_COMMIT() asm volatile("cp.async.commit_group;" ::: "memory")
#define CP_WAIT(n)  asm volatile("cp.async.wait_group %0;" :: "n"(n) : "memory")

#define LDMATRIX_X4(r, addr) \
    asm volatile("ldmatrix.sync.aligned.m8n8.x4.shared.b16 {%0,%1,%2,%3}, [%4];" \
                 : "=r"((r)[0]), "=r"((r)[1]), "=r"((r)[2]), "=r"((r)[3]) \
                 : "r"(addr))

// D += A(16x32 s8, row-major) * B(8x32 s8, n-major rows of k)
__device__ __forceinline__ void mma_s8(int* d, const uint32_t* a,
                                       uint32_t b0, uint32_t b1) {
    asm volatile(
        "mma.sync.aligned.m16n8k32.row.col.s32.s8.s8.s32 "
        "{%0,%1,%2,%3}, {%4,%5,%6,%7}, {%8,%9}, {%0,%1,%2,%3};"
        : "+r"(d[0]), "+r"(d[1]), "+r"(d[2]), "+r"(d[3])
        : "r"(a[0]), "r"(a[1]), "r"(a[2]), "r"(a[3]),
          "r"(b0), "r"(b1));
}

// ============================================================
// Quantization pre-pass kernels (HBM streaming)
// ============================================================
__device__ __forceinline__ uint32_t pack4(float4 v, float s) {
    int a = __float2int_rn(v.x / s);
    int b = __float2int_rn(v.y / s);
    int c = __float2int_rn(v.z / s);
    int d = __float2int_rn(v.w / s);
    a = max(-128, min(127, a));
    b = max(-128, min(127, b));
    c = max(-128, min(127, c));
    d = max(-128, min(127, d));
    return (uint32_t)(a & 0xFF) | ((uint32_t)(b & 0xFF) << 8) |
           ((uint32_t)(c & 0xFF) << 16) | ((uint32_t)(d & 0xFF) << 24);
}

__global__ void quantize_x_kernel(const float4* __restrict__ x4,
                                  const float* __restrict__ xs_ptr, int n4) {
    int i = blockIdx.x * blockDim.x + threadIdx.x;
    if (i >= n4) return;
    float s = __ldg(xs_ptr);
    reinterpret_cast<uint32_t*>(g_xq)[i] = pack4(x4[i], s);
}

__global__ void quantize_w_kernel(const float4* __restrict__ w4, int n4) {
    int i = blockIdx.x * blockDim.x + threadIdx.x;
    if (i >= n4) return;
    reinterpret_cast<uint32_t*>(g_wq)[i] = pack4(w4[i], 1.0f);
}

// ============================================================
// GEMM kernel
//   512 threads = 16 warps, warp grid 4(m) x 4(n), warp tile 32x64.
//   SMEM: sc[256]f32 | bias[256]f32 | 3 stages of (A 128x128B + B 256x128B)
//   SW128-style XOR swizzle on 16B chunks -> conflict-free ldmatrix.
// ============================================================
#define SOFF_SC   0
#define SOFF_BI   1024
#define SOFF_ST   2048
#define STAGE_BYTES ((BM + BN) * BK)         // 49152
#define ASTAGE(s) (SOFF_ST + (s) * STAGE_BYTES)
#define BSTAGE(s) (ASTAGE(s) + BM * BK)
#define SMEM_TOTAL (SOFF_ST + STAGES * STAGE_BYTES)   // 149504

__device__ __forceinline__ void load_stage(uint32_t sb, int s, int kiter,
                                           int m0, int n0, int tid) {
    int k0 = kiter * BK;
    const int8_t* Ab = g_xq + (size_t)m0 * KK + k0;
    const int8_t* Bb = g_wq + (size_t)n0 * KK + k0;
    #pragma unroll
    for (int i = 0; i < (BM + BN) * 8 / NTHREADS; i++) {   // 6
        int idx = tid + i * NTHREADS;
        int row = idx >> 3;
        int c = idx & 7;
        if (row < BM) {
            cp_async16(sb + ASTAGE(s) + row * 128 + ((c ^ (row & 7)) << 4),
                       Ab + (size_t)row * KK + c * 16);
        } else {
            int br = row - BM;
            cp_async16(sb + BSTAGE(s) + br * 128 + ((c ^ (br & 7)) << 4),
                       Bb + (size_t)br * KK + c * 16);
        }
    }
}

__global__ void __launch_bounds__(NTHREADS, 1)
w8a8_gemm_kernel(float* __restrict__ out,
                 const float* __restrict__ wsc,
                 const float* __restrict__ bias,
                 const float* __restrict__ xs_ptr) {
    extern __shared__ char smem[];
    uint32_t sb = smem_to_u32(smem);
    int tid  = threadIdx.x;
    int wid  = tid >> 5;
    int lane = tid & 31;
    int warp_m = wid & 3;     // 0..3  -> m offset warp_m*32
    int warp_n = wid >> 2;    // 0..3  -> n offset warp_n*64

    int m0 = blockIdx.y * BM;
    int n0 = blockIdx.x * BN;

    // stage epilogue scale/bias (read after first __syncthreads)
    for (int c = tid; c < BN; c += NTHREADS) {
        reinterpret_cast<float*>(smem + SOFF_SC)[c] = wsc[n0 + c];
        reinterpret_cast<float*>(smem + SOFF_BI)[c] = bias[n0 + c];
    }

    // pipeline prologue: stages 0, 1
    load_stage(sb, 0, 0, m0, n0, tid);
    CP_COMMIT();
    load_stage(sb, 1, 1, m0, n0, tid);
    CP_COMMIT();

    int acc[2][8][4] = {};

    // ldmatrix lane address components
    int arow  = lane & 15;              // A: rows 0..15 within m16 tile
    int ahalf = lane >> 4;              // A: 16B half within k32 chunk
    int brow  = (lane & 7) + ((lane & 16) >> 1);  // B: rows 0..15 within n16
    int bhalf = (lane >> 3) & 1;        // B: 16B half

    for (int kit = 0; kit < KITERS; kit++) {
        CP_WAIT(STAGES - 2);
        __syncthreads();

        int knext = kit + STAGES - 1;
        if (knext < KITERS) {
            load_stage(sb, knext % STAGES, knext, m0, n0, tid);
            CP_COMMIT();
        }

        int s = kit % STAGES;
        uint32_t As = sb + ASTAGE(s);
        uint32_t Bs = sb + BSTAGE(s);

        #pragma unroll
        for (int j = 0; j < BK / 32; j++) {      // 4 k32 steps
            uint32_t a[2][4];
            #pragma unroll
            for (int t = 0; t < 2; t++) {
                int row = warp_m * 32 + t * 16 + arow;
                int chunk = (j * 2 + ahalf) ^ (row & 7);
                LDMATRIX_X4(a[t], As + row * 128 + (chunk << 4));
            }
            uint32_t b[4][4];
            #pragma unroll
            for (int p = 0; p < 4; p++) {
                int row = warp_n * 64 + p * 16 + brow;
                int chunk = (j * 2 + bhalf) ^ (row & 7);
                LDMATRIX_X4(b[p], Bs + row * 128 + (chunk << 4));
            }
            #pragma unroll
            for (int t = 0; t < 2; t++) {
                #pragma unroll
                for (int p = 0; p < 4; p++) {
                    mma_s8(acc[t][2 * p],     a[t], b[p][0], b[p][1]);
                    mma_s8(acc[t][2 * p + 1], a[t], b[p][2], b[p][3]);
                }
            }
        }
    }

    // -------- epilogue: out = acc * xs * sc[n] + bias[n] --------
    float xs = __ldg(xs_ptr);
    const float* sc = reinterpret_cast<const float*>(smem + SOFF_SC);
    const float* bi = reinterpret_cast<const float*>(smem + SOFF_BI);

    int rbase = m0 + warp_m * 32 + (lane >> 2);
    #pragma unroll
    for (int t = 0; t < 2; t++) {
        #pragma unroll
        for (int q = 0; q < 8; q++) {
            int col = warp_n * 64 + q * 8 + (lane & 3) * 2;
            float s0 = xs * sc[col],     s1 = xs * sc[col + 1];
            float b0 = bi[col],          b1 = bi[col + 1];
            int row = rbase + t * 16;
            float2 v0, v1;
            v0.x = (float)acc[t][q][0] * s0 + b0;
            v0.y = (float)acc[t][q][1] * s1 + b1;
            v1.x = (float)acc[t][q][2] * s0 + b0;
            v1.y = (float)acc[t][q][3] * s1 + b1;
            *reinterpret_cast<float2*>(out + (size_t)row * NN + n0 + col) = v0;
            *reinterpret_cast<float2*>(out + (size_t)(row + 8) * NN + n0 + col) = v1;
        }
    }
}

// ============================================================
// kernel_launch
// Inputs: x[8192*4096] f32, weight_int8[4096*4096] f32,
//         w_scale[4096] f32, bias[4096] f32, x_scale[1] f32
// Output: f32 [8192*4096]
// ============================================================
extern "C" void kernel_launch(void* const* d_in, const int* in_sizes, int n_in,
                              void* d_out, int out_size) {
    const float* x    = (const float*)d_in[0];
    const float* w    = (const float*)d_in[1];
    const float* wsc  = (const float*)d_in[2];
    const float* bias = (const float*)d_in[3];
    const float* xs   = (const float*)d_in[4];
    float* out = (float*)d_out;

    {   // quantize activations -> int8 scratch
        int n4 = MM * KK / 4;
        quantize_x_kernel<<<n4 / 256, 256>>>((const float4*)x, xs, n4);
    }
    {   // convert weights -> int8 scratch
        int n4 = NN * KK / 4;
        quantize_w_kernel<<<n4 / 256, 256>>>((const float4*)w, n4);
    }

    static bool attr_set = false;
    if (!attr_set) {
        cudaFuncSetAttribute(w8a8_gemm_kernel,
                             cudaFuncAttributeMaxDynamicSharedMemorySize,
                             SMEM_TOTAL);
        attr_set = true;
    }
    dim3 grid(NN / BN, MM / BM);   // (16, 64)
    w8a8_gemm_kernel<<<grid, NTHREADS, SMEM_TOTAL>>>(out, wsc, bias, xs);
}

// round 3
// speedup vs baseline: 2.6124x; 2.6124x over previous
#include <cuda_runtime.h>
#include <cuda_bf16.h>
#include <cstdint>

// ============================================================
// W8A8 linear: out[M,N] = xs * (Xq[M,K] @ Wq[N,K]^T) * wsc[n] + bias[n]
//   M = 8192, N = 4096, K = 4096
// Base-sm_103 path (harness compiles via compute_103 -> no tcgen05,
// and mma.sync.s8 is dp4a-EMULATED there). Use bf16 HMMA instead:
// quantized operands are exact small integers -> exact in bf16,
// fp32 accumulation exact at these magnitudes.
// ============================================================

#define MM 8192
#define NN 4096
#define KK 4096

#define BM 128
#define BN 256
#define BK 64                 // bf16 elements; 128 bytes per row
#define STAGES 3
#define KITERS (KK / BK)      // 64
#define NTHREADS 512

// ---- device scratch: quantized bf16 operands ----
__device__ __align__(128) __nv_bfloat16 g_xq[(size_t)MM * KK];
__device__ __align__(128) __nv_bfloat16 g_wq[(size_t)NN * KK];

// ============================================================
// PTX helpers (base-arch only)
// ============================================================
__device__ __forceinline__ uint32_t smem_to_u32(const void* p) {
    uint32_t a;
    asm("{ .reg .u64 t; cvta.to.shared.u64 t, %1; cvt.u32.u64 %0, t; }"
        : "=r"(a) : "l"(p));
    return a;
}

__device__ __forceinline__ void cp_async16(uint32_t dst, const void* src) {
    asm volatile("cp.async.cg.shared.global [%0], [%1], 16;"
                 :: "r"(dst), "l"(src) : "memory");
}
#define CP_COMMIT() asm volatile("cp.async.commit_group;" ::: "memory")
#define CP_WAIT(n)  asm volatile("cp.async.wait_group %0;" :: "n"(n) : "memory")

#define LDMATRIX_X4(r, addr) \
    asm volatile("ldmatrix.sync.aligned.m8n8.x4.shared.b16 {%0,%1,%2,%3}, [%4];" \
                 : "=r"((r)[0]), "=r"((r)[1]), "=r"((r)[2]), "=r"((r)[3]) \
                 : "r"(addr))

// D(16x8 f32) += A(16x16 bf16, row-major) * B(16x8 bf16, col operand)
__device__ __forceinline__ void mma_bf16(float* d, const uint32_t* a,
                                         uint32_t b0, uint32_t b1) {
    asm volatile(
        "mma.sync.aligned.m16n8k16.row.col.f32.bf16.bf16.f32 "
        "{%0,%1,%2,%3}, {%4,%5,%6,%7}, {%8,%9}, {%0,%1,%2,%3};"
        : "+f"(d[0]), "+f"(d[1]), "+f"(d[2]), "+f"(d[3])
        : "r"(a[0]), "r"(a[1]), "r"(a[2]), "r"(a[3]),
          "r"(b0), "r"(b1));
}

// ============================================================
// Quantization pre-pass kernels (HBM streaming), f32 -> bf16 ints
// ============================================================
__device__ __forceinline__ uint2 quant4_bf16(float4 v, float s) {
    float a = fminf(127.f, fmaxf(-128.f, rintf(v.x / s)));
    float b = fminf(127.f, fmaxf(-128.f, rintf(v.y / s)));
    float c = fminf(127.f, fmaxf(-128.f, rintf(v.z / s)));
    float d = fminf(127.f, fmaxf(-128.f, rintf(v.w / s)));
    __nv_bfloat162 lo = __floats2bfloat162_rn(a, b);
    __nv_bfloat162 hi = __floats2bfloat162_rn(c, d);
    uint2 p;
    p.x = *reinterpret_cast<uint32_t*>(&lo);
    p.y = *reinterpret_cast<uint32_t*>(&hi);
    return p;
}

__global__ void quantize_x_kernel(const float4* __restrict__ x4,
                                  const float* __restrict__ xs_ptr, int n4) {
    int i = blockIdx.x * blockDim.x + threadIdx.x;
    if (i >= n4) return;
    float s = __ldg(xs_ptr);
    reinterpret_cast<uint2*>(g_xq)[i] = quant4_bf16(x4[i], s);
}

__global__ void quantize_w_kernel(const float4* __restrict__ w4, int n4) {
    int i = blockIdx.x * blockDim.x + threadIdx.x;
    if (i >= n4) return;
    float4 v = w4[i];   // already integer-valued
    __nv_bfloat162 lo = __floats2bfloat162_rn(v.x, v.y);
    __nv_bfloat162 hi = __floats2bfloat162_rn(v.z, v.w);
    uint2 p;
    p.x = *reinterpret_cast<uint32_t*>(&lo);
    p.y = *reinterpret_cast<uint32_t*>(&hi);
    reinterpret_cast<uint2*>(g_wq)[i] = p;
}

// ============================================================
// GEMM kernel
//   512 threads = 16 warps, warp grid 4(m) x 4(n), warp tile 32x64.
//   SMEM: sc[256]f32 | bias[256]f32 | 3 stages of (A 128x128B + B 256x128B)
//   Rows are 128B (= 64 bf16 = BK); 16B-chunk XOR swizzle -> conflict-free
//   ldmatrix. A k16 step = 32B = chunks {2j, 2j+1}.
// ============================================================
#define SOFF_SC   0
#define SOFF_BI   1024
#define SOFF_ST   2048
#define STAGE_BYTES ((BM + BN) * 128)        // 49152
#define ASTAGE(s) (SOFF_ST + (s) * STAGE_BYTES)
#define BSTAGE(s) (ASTAGE(s) + BM * 128)
#define SMEM_TOTAL (SOFF_ST + STAGES * STAGE_BYTES)   // 149504

__device__ __forceinline__ void load_stage(uint32_t sb, int s, int kiter,
                                           int m0, int n0, int tid) {
    int k0 = kiter * BK;
    const __nv_bfloat16* Ab = g_xq + (size_t)m0 * KK + k0;
    const __nv_bfloat16* Bb = g_wq + (size_t)n0 * KK + k0;
    #pragma unroll
    for (int i = 0; i < (BM + BN) * 8 / NTHREADS; i++) {   // 6
        int idx = tid + i * NTHREADS;
        int row = idx >> 3;
        int c = idx & 7;                                   // 16B chunk (8 bf16)
        if (row < BM) {
            cp_async16(sb + ASTAGE(s) + row * 128 + ((c ^ (row & 7)) << 4),
                       Ab + (size_t)row * KK + c * 8);
        } else {
            int br = row - BM;
            cp_async16(sb + BSTAGE(s) + br * 128 + ((c ^ (br & 7)) << 4),
                       Bb + (size_t)br * KK + c * 8);
        }
    }
}

__global__ void __launch_bounds__(NTHREADS, 1)
w8a8_gemm_kernel(float* __restrict__ out,
                 const float* __restrict__ wsc,
                 const float* __restrict__ bias,
                 const float* __restrict__ xs_ptr) {
    extern __shared__ char smem[];
    uint32_t sb = smem_to_u32(smem);
    int tid  = threadIdx.x;
    int wid  = tid >> 5;
    int lane = tid & 31;
    int warp_m = wid & 3;     // m offset warp_m*32
    int warp_n = wid >> 2;    // n offset warp_n*64

    int m0 = blockIdx.y * BM;
    int n0 = blockIdx.x * BN;

    // stage epilogue scale/bias (read after loop's syncthreads)
    for (int c = tid; c < BN; c += NTHREADS) {
        reinterpret_cast<float*>(smem + SOFF_SC)[c] = wsc[n0 + c];
        reinterpret_cast<float*>(smem + SOFF_BI)[c] = bias[n0 + c];
    }

    // pipeline prologue: stages 0, 1
    load_stage(sb, 0, 0, m0, n0, tid);
    CP_COMMIT();
    load_stage(sb, 1, 1, m0, n0, tid);
    CP_COMMIT();

    float acc[2][8][4] = {};

    // ldmatrix lane address components (matches mma fragment order)
    int arow  = lane & 15;                        // A rows within m16
    int ahalf = lane >> 4;                        // A 16B half of k16 (32B)
    int brow  = (lane & 7) + ((lane & 16) >> 1);  // B n-rows (two n8 tiles)
    int bhalf = (lane >> 3) & 1;                  // B 16B half of k16

    for (int kit = 0; kit < KITERS; kit++) {
        CP_WAIT(STAGES - 2);
        __syncthreads();

        int knext = kit + STAGES - 1;
        if (knext < KITERS) {
            load_stage(sb, knext % STAGES, knext, m0, n0, tid);
            CP_COMMIT();
        }

        int s = kit % STAGES;
        uint32_t As = sb + ASTAGE(s);
        uint32_t Bs = sb + BSTAGE(s);

        #pragma unroll
        for (int j = 0; j < BK / 16; j++) {      // 4 k16 steps
            uint32_t a[2][4];
            #pragma unroll
            for (int t = 0; t < 2; t++) {
                int row = warp_m * 32 + t * 16 + arow;
                int chunk = (j * 2 + ahalf) ^ (row & 7);
                LDMATRIX_X4(a[t], As + row * 128 + (chunk << 4));
            }
            uint32_t b[4][4];
            #pragma unroll
            for (int p = 0; p < 4; p++) {
                int row = warp_n * 64 + p * 16 + brow;
                int chunk = (j * 2 + bhalf) ^ (row & 7);
                LDMATRIX_X4(b[p], Bs + row * 128 + (chunk << 4));
            }
            #pragma unroll
            for (int t = 0; t < 2; t++) {
                #pragma unroll
                for (int p = 0; p < 4; p++) {
                    mma_bf16(acc[t][2 * p],     a[t], b[p][0], b[p][1]);
                    mma_bf16(acc[t][2 * p + 1], a[t], b[p][2], b[p][3]);
                }
            }
        }
    }

    // -------- epilogue: out = acc * xs * sc[n] + bias[n] --------
    float xs = __ldg(xs_ptr);
    const float* sc = reinterpret_cast<const float*>(smem + SOFF_SC);
    const float* bi = reinterpret_cast<const float*>(smem + SOFF_BI);

    int rbase = m0 + warp_m * 32 + (lane >> 2);
    #pragma unroll
    for (int t = 0; t < 2; t++) {
        #pragma unroll
        for (int q = 0; q < 8; q++) {
            int col = warp_n * 64 + q * 8 + (lane & 3) * 2;
            float s0 = xs * sc[col],     s1 = xs * sc[col + 1];
            float b0 = bi[col],          b1 = bi[col + 1];
            int row = rbase + t * 16;
            float2 v0, v1;
            v0.x = acc[t][q][0] * s0 + b0;
            v0.y = acc[t][q][1] * s1 + b1;
            v1.x = acc[t][q][2] * s0 + b0;
            v1.y = acc[t][q][3] * s1 + b1;
            *reinterpret_cast<float2*>(out + (size_t)row * NN + n0 + col) = v0;
            *reinterpret_cast<float2*>(out + (size_t)(row + 8) * NN + n0 + col) = v1;
        }
    }
}

// ============================================================
// kernel_launch
// Inputs: x[8192*4096] f32, weight_int8[4096*4096] f32,
//         w_scale[4096] f32, bias[4096] f32, x_scale[1] f32
// Output: f32 [8192*4096]
// ============================================================
extern "C" void kernel_launch(void* const* d_in, const int* in_sizes, int n_in,
                              void* d_out, int out_size) {
    const float* x    = (const float*)d_in[0];
    const float* w    = (const float*)d_in[1];
    const float* wsc  = (const float*)d_in[2];
    const float* bias = (const float*)d_in[3];
    const float* xs   = (const float*)d_in[4];
    float* out = (float*)d_out;

    {   // quantize activations -> bf16 scratch
        int n4 = MM * KK / 4;
        quantize_x_kernel<<<n4 / 256, 256>>>((const float4*)x, xs, n4);
    }
    {   // convert weights -> bf16 scratch
        int n4 = NN * KK / 4;
        quantize_w_kernel<<<n4 / 256, 256>>>((const float4*)w, n4);
    }

    static bool attr_set = false;
    if (!attr_set) {
        cudaFuncSetAttribute(w8a8_gemm_kernel,
                             cudaFuncAttributeMaxDynamicSharedMemorySize,
                             SMEM_TOTAL);
        attr_set = true;
    }
    dim3 grid(NN / BN, MM / BM);   // (16, 64)
    w8a8_gemm_kernel<<<grid, NTHREADS, SMEM_TOTAL>>>(out, wsc, bias, xs);
}

// round 4
// speedup vs baseline: 2.6827x; 1.0269x over previous
#include <cuda_runtime.h>
#include <cuda_bf16.h>
#include <cstdint>

// ============================================================
// W8A8 linear: out[M,N] = xs * (Xq[M,K] @ Wq[N,K]^T) * wsc[n] + bias[n]
//   M = 8192, N = 4096, K = 4096
// Base-sm_103 (compute_103 virtual arch): bf16 HMMA via mma.sync,
// cp.async 3-stage pipeline, ldmatrix with XOR swizzle.
// Round 4: 8 warps x (64x64) warp tiles -> halve ldmatrix traffic
// (smem crossbar was the binder at 16 x (32x64)).
// ============================================================

#define MM 8192
#define NN 4096
#define KK 4096

#define BM 128
#define BN 256
#define BK 64                 // bf16 elements; 128 bytes per row
#define STAGES 3
#define KITERS (KK / BK)      // 64
#define NTHREADS 256          // 8 warps

// ---- device scratch: quantized bf16 operands ----
__device__ __align__(128) __nv_bfloat16 g_xq[(size_t)MM * KK];
__device__ __align__(128) __nv_bfloat16 g_wq[(size_t)NN * KK];

// ============================================================
// PTX helpers (base-arch only)
// ============================================================
__device__ __forceinline__ uint32_t smem_to_u32(const void* p) {
    uint32_t a;
    asm("{ .reg .u64 t; cvta.to.shared.u64 t, %1; cvt.u32.u64 %0, t; }"
        : "=r"(a) : "l"(p));
    return a;
}

__device__ __forceinline__ void cp_async16(uint32_t dst, const void* src) {
    asm volatile("cp.async.cg.shared.global [%0], [%1], 16;"
                 :: "r"(dst), "l"(src) : "memory");
}
#define CP_COMMIT() asm volatile("cp.async.commit_group;" ::: "memory")
#define CP_WAIT(n)  asm volatile("cp.async.wait_group %0;" :: "n"(n) : "memory")

#define LDMATRIX_X4(r, addr) \
    asm volatile("ldmatrix.sync.aligned.m8n8.x4.shared.b16 {%0,%1,%2,%3}, [%4];" \
                 : "=r"((r)[0]), "=r"((r)[1]), "=r"((r)[2]), "=r"((r)[3]) \
                 : "r"(addr))

// D(16x8 f32) += A(16x16 bf16, row-major) * B(16x8 bf16, col operand)
__device__ __forceinline__ void mma_bf16(float* d, const uint32_t* a,
                                         uint32_t b0, uint32_t b1) {
    asm volatile(
        "mma.sync.aligned.m16n8k16.row.col.f32.bf16.bf16.f32 "
        "{%0,%1,%2,%3}, {%4,%5,%6,%7}, {%8,%9}, {%0,%1,%2,%3};"
        : "+f"(d[0]), "+f"(d[1]), "+f"(d[2]), "+f"(d[3])
        : "r"(a[0]), "r"(a[1]), "r"(a[2]), "r"(a[3]),
          "r"(b0), "r"(b1));
}

// ============================================================
// Quantization pre-pass kernels (HBM streaming), f32 -> bf16 ints
// ============================================================
__device__ __forceinline__ uint2 quant4_bf16(float4 v, float s) {
    float a = fminf(127.f, fmaxf(-128.f, rintf(v.x / s)));
    float b = fminf(127.f, fmaxf(-128.f, rintf(v.y / s)));
    float c = fminf(127.f, fmaxf(-128.f, rintf(v.z / s)));
    float d = fminf(127.f, fmaxf(-128.f, rintf(v.w / s)));
    __nv_bfloat162 lo = __floats2bfloat162_rn(a, b);
    __nv_bfloat162 hi = __floats2bfloat162_rn(c, d);
    uint2 p;
    p.x = *reinterpret_cast<uint32_t*>(&lo);
    p.y = *reinterpret_cast<uint32_t*>(&hi);
    return p;
}

__global__ void quantize_x_kernel(const float4* __restrict__ x4,
                                  const float* __restrict__ xs_ptr, int n4) {
    int i = blockIdx.x * blockDim.x + threadIdx.x;
    if (i >= n4) return;
    float s = __ldg(xs_ptr);
    reinterpret_cast<uint2*>(g_xq)[i] = quant4_bf16(x4[i], s);
}

__global__ void quantize_w_kernel(const float4* __restrict__ w4, int n4) {
    int i = blockIdx.x * blockDim.x + threadIdx.x;
    if (i >= n4) return;
    float4 v = w4[i];   // already integer-valued
    __nv_bfloat162 lo = __floats2bfloat162_rn(v.x, v.y);
    __nv_bfloat162 hi = __floats2bfloat162_rn(v.z, v.w);
    uint2 p;
    p.x = *reinterpret_cast<uint32_t*>(&lo);
    p.y = *reinterpret_cast<uint32_t*>(&hi);
    reinterpret_cast<uint2*>(g_wq)[i] = p;
}

// ============================================================
// GEMM kernel
//   256 threads = 8 warps, warp grid 2(m) x 4(n), warp tile 64x64.
//   SMEM: sc[256]f32 | bias[256]f32 | 3 stages of (A 128x128B + B 256x128B)
//   Rows are 128B (= 64 bf16 = BK); 16B-chunk XOR swizzle -> conflict-free
//   ldmatrix. A k16 step = 32B = chunks {2j, 2j+1}.
// ============================================================
#define SOFF_SC   0
#define SOFF_BI   1024
#define SOFF_ST   2048
#define STAGE_BYTES ((BM + BN) * 128)        // 49152
#define ASTAGE(s) (SOFF_ST + (s) * STAGE_BYTES)
#define BSTAGE(s) (ASTAGE(s) + BM * 128)
#define SMEM_TOTAL (SOFF_ST + STAGES * STAGE_BYTES)   // 149504

__device__ __forceinline__ void load_stage(uint32_t sb, int s, int kiter,
                                           int m0, int n0, int tid) {
    int k0 = kiter * BK;
    const __nv_bfloat16* Ab = g_xq + (size_t)m0 * KK + k0;
    const __nv_bfloat16* Bb = g_wq + (size_t)n0 * KK + k0;
    #pragma unroll
    for (int i = 0; i < (BM + BN) * 8 / NTHREADS; i++) {   // 12
        int idx = tid + i * NTHREADS;
        int row = idx >> 3;
        int c = idx & 7;                                   // 16B chunk (8 bf16)
        if (row < BM) {
            cp_async16(sb + ASTAGE(s) + row * 128 + ((c ^ (row & 7)) << 4),
                       Ab + (size_t)row * KK + c * 8);
        } else {
            int br = row - BM;
            cp_async16(sb + BSTAGE(s) + br * 128 + ((c ^ (br & 7)) << 4),
                       Bb + (size_t)br * KK + c * 8);
        }
    }
}

__global__ void __launch_bounds__(NTHREADS, 1)
w8a8_gemm_kernel(float* __restrict__ out,
                 const float* __restrict__ wsc,
                 const float* __restrict__ bias,
                 const float* __restrict__ xs_ptr) {
    extern __shared__ char smem[];
    uint32_t sb = smem_to_u32(smem);
    int tid  = threadIdx.x;
    int wid  = tid >> 5;
    int lane = tid & 31;
    int warp_m = wid & 1;     // m offset warp_m*64
    int warp_n = wid >> 1;    // n offset warp_n*64

    int m0 = blockIdx.y * BM;
    int n0 = blockIdx.x * BN;

    // stage epilogue scale/bias (read after loop's syncthreads)
    for (int c = tid; c < BN; c += NTHREADS) {
        reinterpret_cast<float*>(smem + SOFF_SC)[c] = wsc[n0 + c];
        reinterpret_cast<float*>(smem + SOFF_BI)[c] = bias[n0 + c];
    }

    // pipeline prologue: stages 0, 1
    load_stage(sb, 0, 0, m0, n0, tid);
    CP_COMMIT();
    load_stage(sb, 1, 1, m0, n0, tid);
    CP_COMMIT();

    float acc[4][8][4] = {};   // [m16 tile][n8 tile][frag]

    // ldmatrix lane address components (matches mma fragment order)
    int arow  = lane & 15;                        // A rows within m16
    int ahalf = lane >> 4;                        // A 16B half of k16 (32B)
    int brow  = (lane & 7) + ((lane & 16) >> 1);  // B n-rows (two n8 tiles)
    int bhalf = (lane >> 3) & 1;                  // B 16B half of k16

    for (int kit = 0; kit < KITERS; kit++) {
        CP_WAIT(STAGES - 2);
        __syncthreads();

        int knext = kit + STAGES - 1;
        if (knext < KITERS) {
            load_stage(sb, knext % STAGES, knext, m0, n0, tid);
            CP_COMMIT();
        }

        int s = kit % STAGES;
        uint32_t As = sb + ASTAGE(s);
        uint32_t Bs = sb + BSTAGE(s);

        #pragma unroll
        for (int j = 0; j < BK / 16; j++) {      // 4 k16 steps
            uint32_t a[4][4];
            #pragma unroll
            for (int t = 0; t < 4; t++) {
                int row = warp_m * 64 + t * 16 + arow;
                int chunk = (j * 2 + ahalf) ^ (row & 7);
                LDMATRIX_X4(a[t], As + row * 128 + (chunk << 4));
            }
            uint32_t b[4][4];
            #pragma unroll
            for (int p = 0; p < 4; p++) {
                int row = warp_n * 64 + p * 16 + brow;
                int chunk = (j * 2 + bhalf) ^ (row & 7);
                LDMATRIX_X4(b[p], Bs + row * 128 + (chunk << 4));
            }
            #pragma unroll
            for (int t = 0; t < 4; t++) {
                #pragma unroll
                for (int p = 0; p < 4; p++) {
                    mma_bf16(acc[t][2 * p],     a[t], b[p][0], b[p][1]);
                    mma_bf16(acc[t][2 * p + 1], a[t], b[p][2], b[p][3]);
                }
            }
        }
    }

    // -------- epilogue: out = acc * xs * sc[n] + bias[n] --------
    float xs = __ldg(xs_ptr);
    const float* sc = reinterpret_cast<const float*>(smem + SOFF_SC);
    const float* bi = reinterpret_cast<const float*>(smem + SOFF_BI);

    int rbase = m0 + warp_m * 64 + (lane >> 2);
    #pragma unroll
    for (int t = 0; t < 4; t++) {
        #pragma unroll
        for (int q = 0; q < 8; q++) {
            int col = warp_n * 64 + q * 8 + (lane & 3) * 2;
            float s0 = xs * sc[col],     s1 = xs * sc[col + 1];
            float b0 = bi[col],          b1 = bi[col + 1];
            int row = rbase + t * 16;
            float2 v0, v1;
            v0.x = acc[t][q][0] * s0 + b0;
            v0.y = acc[t][q][1] * s1 + b1;
            v1.x = acc[t][q][2] * s0 + b0;
            v1.y = acc[t][q][3] * s1 + b1;
            *reinterpret_cast<float2*>(out + (size_t)row * NN + n0 + col) = v0;
            *reinterpret_cast<float2*>(out + (size_t)(row + 8) * NN + n0 + col) = v1;
        }
    }
}

// ============================================================
// kernel_launch
// Inputs: x[8192*4096] f32, weight_int8[4096*4096] f32,
//         w_scale[4096] f32, bias[4096] f32, x_scale[1] f32
// Output: f32 [8192*4096]
// ============================================================
extern "C" void kernel_launch(void* const* d_in, const int* in_sizes, int n_in,
                              void* d_out, int out_size) {
    const float* x    = (const float*)d_in[0];
    const float* w    = (const float*)d_in[1];
    const float* wsc  = (const float*)d_in[2];
    const float* bias = (const float*)d_in[3];
    const float* xs   = (const float*)d_in[4];
    float* out = (float*)d_out;

    {   // quantize activations -> bf16 scratch
        int n4 = MM * KK / 4;
        quantize_x_kernel<<<n4 / 256, 256>>>((const float4*)x, xs, n4);
    }
    {   // convert weights -> bf16 scratch
        int n4 = NN * KK / 4;
        quantize_w_kernel<<<n4 / 256, 256>>>((const float4*)w, n4);
    }

    static bool attr_set = false;
    if (!attr_set) {
        cudaFuncSetAttribute(w8a8_gemm_kernel,
                             cudaFuncAttributeMaxDynamicSharedMemorySize,
                             SMEM_TOTAL);
        attr_set = true;
    }
    dim3 grid(NN / BN, MM / BM);   // (16, 64)
    w8a8_gemm_kernel<<<grid, NTHREADS, SMEM_TOTAL>>>(out, wsc, bias, xs);
}

// round 5
// speedup vs baseline: 2.7586x; 1.0283x over previous
#include <cuda_runtime.h>
#include <cuda_bf16.h>
#include <cstdint>

// ============================================================
// W8A8 linear: out[M,N] = xs * (Xq[M,K] @ Wq[N,K]^T) * wsc[n] + bias[n]
//   M = 8192, N = 4096, K = 4096
// Base-sm_103 (compute_103 virtual arch): bf16 HMMA via mma.sync.
// Round 5: persistent CTAs + continuous cross-tile cp.async cursor
// (epilogue overlaps next tile's loads), 4-stage pipeline, fused
// quantize kernel (also makes ncu -s 5 land on the GEMM).
// ============================================================

#define MM 8192
#define NN 4096
#define KK 4096

#define BM 128
#define BN 256
#define BK 64                 // bf16 elements; 128 bytes per row
#define STAGES 4
#define KITERS (KK / BK)      // 64
#define NTHREADS 256          // 8 warps
#define TILES_X (NN / BN)     // 16
#define NTILES ((MM / BM) * (NN / BN))   // 1024

// ---- device scratch: quantized bf16 operands ----
__device__ __align__(128) __nv_bfloat16 g_xq[(size_t)MM * KK];
__device__ __align__(128) __nv_bfloat16 g_wq[(size_t)NN * KK];

// ============================================================
// PTX helpers (base-arch only)
// ============================================================
__device__ __forceinline__ uint32_t smem_to_u32(const void* p) {
    uint32_t a;
    asm("{ .reg .u64 t; cvta.to.shared.u64 t, %1; cvt.u32.u64 %0, t; }"
        : "=r"(a) : "l"(p));
    return a;
}

__device__ __forceinline__ void cp_async16(uint32_t dst, const void* src) {
    asm volatile("cp.async.cg.shared.global [%0], [%1], 16;"
                 :: "r"(dst), "l"(src) : "memory");
}
#define CP_COMMIT() asm volatile("cp.async.commit_group;" ::: "memory")
#define CP_WAIT(n)  asm volatile("cp.async.wait_group %0;" :: "n"(n) : "memory")

#define LDMATRIX_X4(r, addr) \
    asm volatile("ldmatrix.sync.aligned.m8n8.x4.shared.b16 {%0,%1,%2,%3}, [%4];" \
                 : "=r"((r)[0]), "=r"((r)[1]), "=r"((r)[2]), "=r"((r)[3]) \
                 : "r"(addr))

// D(16x8 f32) += A(16x16 bf16, row-major) * B(16x8 bf16, col operand)
__device__ __forceinline__ void mma_bf16(float* d, const uint32_t* a,
                                         uint32_t b0, uint32_t b1) {
    asm volatile(
        "mma.sync.aligned.m16n8k16.row.col.f32.bf16.bf16.f32 "
        "{%0,%1,%2,%3}, {%4,%5,%6,%7}, {%8,%9}, {%0,%1,%2,%3};"
        : "+f"(d[0]), "+f"(d[1]), "+f"(d[2]), "+f"(d[3])
        : "r"(a[0]), "r"(a[1]), "r"(a[2]), "r"(a[3]),
          "r"(b0), "r"(b1));
}

// ============================================================
// Fused quantization pre-pass (x -> g_xq scaled; w -> g_wq passthrough)
// ============================================================
__device__ __forceinline__ uint2 quant4_bf16(float4 v, float s) {
    float a = fminf(127.f, fmaxf(-128.f, rintf(v.x / s)));
    float b = fminf(127.f, fmaxf(-128.f, rintf(v.y / s)));
    float c = fminf(127.f, fmaxf(-128.f, rintf(v.z / s)));
    float d = fminf(127.f, fmaxf(-128.f, rintf(v.w / s)));
    __nv_bfloat162 lo = __floats2bfloat162_rn(a, b);
    __nv_bfloat162 hi = __floats2bfloat162_rn(c, d);
    uint2 p;
    p.x = *reinterpret_cast<uint32_t*>(&lo);
    p.y = *reinterpret_cast<uint32_t*>(&hi);
    return p;
}

__global__ void quantize_kernel(const float4* __restrict__ x4,
                                const float4* __restrict__ w4,
                                const float* __restrict__ xs_ptr,
                                int n4x, int n4tot) {
    int i = blockIdx.x * blockDim.x + threadIdx.x;
    if (i >= n4tot) return;
    if (i < n4x) {
        float s = __ldg(xs_ptr);
        reinterpret_cast<uint2*>(g_xq)[i] = quant4_bf16(x4[i], s);
    } else {
        int j = i - n4x;
        float4 v = w4[j];   // already integer-valued
        __nv_bfloat162 lo = __floats2bfloat162_rn(v.x, v.y);
        __nv_bfloat162 hi = __floats2bfloat162_rn(v.z, v.w);
        uint2 p;
        p.x = *reinterpret_cast<uint32_t*>(&lo);
        p.y = *reinterpret_cast<uint32_t*>(&hi);
        reinterpret_cast<uint2*>(g_wq)[j] = p;
    }
}

// ============================================================
// GEMM kernel: persistent CTAs, 4-stage cp.async ring that runs
// CONTINUOUSLY across tiles (loads for tile t+1 overlap epilogue of t).
//   256 threads = 8 warps, warp grid 2(m) x 4(n), warp tile 64x64.
//   SMEM: sc[256]f32 | bias[256]f32 | 4 stages of (A 128x128B + B 256x128B)
// ============================================================
#define SOFF_SC   0
#define SOFF_BI   1024
#define SOFF_ST   2048
#define STAGE_BYTES ((BM + BN) * 128)        // 49152
#define ASTAGE(s) (SOFF_ST + (s) * STAGE_BYTES)
#define BSTAGE(s) (ASTAGE(s) + BM * 128)
#define SMEM_TOTAL (SOFF_ST + STAGES * STAGE_BYTES)   // 198656

__device__ __forceinline__ void load_stage(uint32_t sb, int s, int kiter,
                                           int m0, int n0, int tid) {
    int k0 = kiter * BK;
    const __nv_bfloat16* Ab = g_xq + (size_t)m0 * KK + k0;
    const __nv_bfloat16* Bb = g_wq + (size_t)n0 * KK + k0;
    #pragma unroll
    for (int i = 0; i < (BM + BN) * 8 / NTHREADS; i++) {   // 12
        int idx = tid + i * NTHREADS;
        int row = idx >> 3;
        int c = idx & 7;                                   // 16B chunk (8 bf16)
        if (row < BM) {
            cp_async16(sb + ASTAGE(s) + row * 128 + ((c ^ (row & 7)) << 4),
                       Ab + (size_t)row * KK + c * 8);
        } else {
            int br = row - BM;
            cp_async16(sb + BSTAGE(s) + br * 128 + ((c ^ (br & 7)) << 4),
                       Bb + (size_t)br * KK + c * 8);
        }
    }
}

__global__ void __launch_bounds__(NTHREADS, 1)
w8a8_gemm_kernel(float* __restrict__ out,
                 const float* __restrict__ wsc,
                 const float* __restrict__ bias,
                 const float* __restrict__ xs_ptr) {
    extern __shared__ char smem[];
    uint32_t sb = smem_to_u32(smem);
    int tid  = threadIdx.x;
    int wid  = tid >> 5;
    int lane = tid & 31;
    int warp_m = wid & 1;     // m offset warp_m*64
    int warp_n = wid >> 1;    // n offset warp_n*64
    int G = gridDim.x;

    // ---- load cursor: continuous across this CTA's tile list ----
    int ltile = blockIdx.x;   // tile id of next load
    int lkit  = 0;            // k-iter of next load
    int ls    = 0;            // stage of next load

    // ---- stage sc/bias for first tile ----
    {
        int n0 = (blockIdx.x % TILES_X) * BN;
        for (int c = tid; c < BN; c += NTHREADS) {
            reinterpret_cast<float*>(smem + SOFF_SC)[c] = wsc[n0 + c];
            reinterpret_cast<float*>(smem + SOFF_BI)[c] = bias[n0 + c];
        }
    }

    // prologue: fill 3 of 4 stages
    #pragma unroll
    for (int p = 0; p < STAGES - 1; p++) {
        if (ltile < NTILES) {
            int lm0 = (ltile / TILES_X) * BM;
            int ln0 = (ltile % TILES_X) * BN;
            load_stage(sb, ls, lkit, lm0, ln0, tid);
            ls = (ls + 1) & (STAGES - 1);
            if (++lkit == KITERS) { lkit = 0; ltile += G; }
        }
        CP_COMMIT();
    }

    float xs = __ldg(xs_ptr);

    // ldmatrix lane address components
    int arow  = lane & 15;                        // A rows within m16
    int ahalf = lane >> 4;                        // A 16B half of k16 (32B)
    int brow  = (lane & 7) + ((lane & 16) >> 1);  // B n-rows (two n8 tiles)
    int bhalf = (lane >> 3) & 1;                  // B 16B half of k16

    int cs = 0;   // compute stage

    for (int mytile = blockIdx.x; mytile < NTILES; mytile += G) {
        int m0 = (mytile / TILES_X) * BM;
        int n0 = (mytile % TILES_X) * BN;

        float acc[4][8][4] = {};   // [m16 tile][n8 tile][frag]

        for (int kit = 0; kit < KITERS; kit++) {
            CP_WAIT(STAGES - 2);
            __syncthreads();

            // issue next load in the continuous stream (3 ahead)
            if (ltile < NTILES) {
                int lm0 = (ltile / TILES_X) * BM;
                int ln0 = (ltile % TILES_X) * BN;
                load_stage(sb, ls, lkit, lm0, ln0, tid);
                ls = (ls + 1) & (STAGES - 1);
                if (++lkit == KITERS) { lkit = 0; ltile += G; }
            }
            CP_COMMIT();

            uint32_t As = sb + ASTAGE(cs);
            uint32_t Bs = sb + BSTAGE(cs);
            cs = (cs + 1) & (STAGES - 1);

            #pragma unroll
            for (int j = 0; j < BK / 16; j++) {      // 4 k16 steps
                uint32_t a[4][4];
                #pragma unroll
                for (int t = 0; t < 4; t++) {
                    int row = warp_m * 64 + t * 16 + arow;
                    int chunk = (j * 2 + ahalf) ^ (row & 7);
                    LDMATRIX_X4(a[t], As + row * 128 + (chunk << 4));
                }
                uint32_t b[4][4];
                #pragma unroll
                for (int p = 0; p < 4; p++) {
                    int row = warp_n * 64 + p * 16 + brow;
                    int chunk = (j * 2 + bhalf) ^ (row & 7);
                    LDMATRIX_X4(b[p], Bs + row * 128 + (chunk << 4));
                }
                #pragma unroll
                for (int t = 0; t < 4; t++) {
                    #pragma unroll
                    for (int p = 0; p < 4; p++) {
                        mma_bf16(acc[t][2 * p],     a[t], b[p][0], b[p][1]);
                        mma_bf16(acc[t][2 * p + 1], a[t], b[p][2], b[p][3]);
                    }
                }
            }
        }

        // -------- epilogue: out = acc * xs * sc[n] + bias[n] --------
        // (next tile's cp.async loads are already in flight underneath)
        const float* sc = reinterpret_cast<const float*>(smem + SOFF_SC);
        const float* bi = reinterpret_cast<const float*>(smem + SOFF_BI);
        int rbase = m0 + warp_m * 64 + (lane >> 2);
        #pragma unroll
        for (int t = 0; t < 4; t++) {
            #pragma unroll
            for (int q = 0; q < 8; q++) {
                int col = warp_n * 64 + q * 8 + (lane & 3) * 2;
                float s0 = xs * sc[col],     s1 = xs * sc[col + 1];
                float b0 = bi[col],          b1 = bi[col + 1];
                int row = rbase + t * 16;
                float2 v0, v1;
                v0.x = acc[t][q][0] * s0 + b0;
                v0.y = acc[t][q][1] * s1 + b1;
                v1.x = acc[t][q][2] * s0 + b0;
                v1.y = acc[t][q][3] * s1 + b1;
                *reinterpret_cast<float2*>(out + (size_t)row * NN + n0 + col) = v0;
                *reinterpret_cast<float2*>(out + (size_t)(row + 8) * NN + n0 + col) = v1;
            }
        }

        // restage sc/bias for next tile (separate smem region from stages)
        int nt = mytile + G;
        if (nt < NTILES) {
            __syncthreads();   // epilogue reads done before overwrite
            int nn0 = (nt % TILES_X) * BN;
            for (int c = tid; c < BN; c += NTHREADS) {
                reinterpret_cast<float*>(smem + SOFF_SC)[c] = wsc[nn0 + c];
                reinterpret_cast<float*>(smem + SOFF_BI)[c] = bias[nn0 + c];
            }
        }
    }
}

// ============================================================
// kernel_launch
// Inputs: x[8192*4096] f32, weight_int8[4096*4096] f32,
//         w_scale[4096] f32, bias[4096] f32, x_scale[1] f32
// Output: f32 [8192*4096]
// ============================================================
extern "C" void kernel_launch(void* const* d_in, const int* in_sizes, int n_in,
                              void* d_out, int out_size) {
    const float* x    = (const float*)d_in[0];
    const float* w    = (const float*)d_in[1];
    const float* wsc  = (const float*)d_in[2];
    const float* bias = (const float*)d_in[3];
    const float* xs   = (const float*)d_in[4];
    float* out = (float*)d_out;

    static int n_sm = 0;
    if (n_sm == 0) {
        cudaDeviceGetAttribute(&n_sm, cudaDevAttrMultiProcessorCount, 0);
        if (n_sm <= 0) n_sm = 148;
        cudaFuncSetAttribute(w8a8_gemm_kernel,
                             cudaFuncAttributeMaxDynamicSharedMemorySize,
                             SMEM_TOTAL);
    }

    // fused quantize pre-pass
    int n4x = MM * KK / 4;
    int n4w = NN * KK / 4;
    int n4tot = n4x + n4w;
    quantize_kernel<<<(n4tot + 255) / 256, 256>>>(
        (const float4*)x, (const float4*)w, xs, n4x, n4tot);

    // persistent GEMM
    int grid = n_sm < NTILES ? n_sm : NTILES;
    w8a8_gemm_kernel<<<grid, NTHREADS, SMEM_TOTAL>>>(out, wsc, bias, xs);
}